// round 16
// baseline (speedup 1.0000x reference)
#include <cuda_runtime.h>
#include <cuda_bf16.h>
#include <stdint.h>
#include <math.h>

#define E_   8
#define M_   1024
#define H_   4096
#define SMAX 16384
#define CAP  2048

// ---------------- device scratch ------------------------------------------------
__device__ int   g_idx[SMAX];
__device__ float g_gate[SMAX];
__device__ float g_gate_sums[E_];
__device__ int   g_kept[E_];
__device__ int   g_slot_token[E_ * CAP];
__device__ float g_slot_gate[E_ * CAP];
__device__ float g_h[(size_t)E_ * CAP * H_];   // fp32 intermediate activations

typedef unsigned long long u64;

// packed f32x2 FMA: elementwise d = a*b + d on both fp32 lanes
#define FMA2(c, a, b) \
    asm("fma.rn.f32x2 %0, %1, %2, %0;" : "+l"(c) : "l"(a), "l"(b))
// duplicate one fp32 into both lanes of a b64
#define DUP2(d, v) \
    asm("mov.b64 %0, {%1, %1};" : "=l"(d) : "f"(v))

__device__ __forceinline__ uint32_t smem_u32(const void* p) {
    uint32_t a;
    asm("{ .reg .u64 t; cvta.to.shared.u64 t, %1; cvt.u32.u64 %0, t; }" : "=r"(a) : "l"(p));
    return a;
}
__device__ __forceinline__ void cp16(uint32_t dst, const void* src) {
    asm volatile("cp.async.cg.shared.global [%0], [%1], 16;" :: "r"(dst), "l"(src));
}
#define CP_COMMIT() asm volatile("cp.async.commit_group;" ::: "memory")
#define CP_WAIT0()  asm volatile("cp.async.wait_group 0;" ::: "memory")

// ---------------- init ----------------------------------------------------------
__global__ void init_kernel() {
    if (threadIdx.x < E_) g_gate_sums[threadIdx.x] = 0.0f;
}

// ---------------- gating (validated R1) ------------------------------------------
__global__ __launch_bounds__(256) void gate_kernel(const float* __restrict__ x,
                                                   const float* __restrict__ wg, int s) {
    __shared__ float swg[M_ * E_];
    __shared__ float bsum[E_];
    int tid = threadIdx.x;
    for (int i = tid; i < M_ * E_; i += 256) swg[i] = wg[i];
    if (tid < E_) bsum[tid] = 0.0f;
    __syncthreads();
    int warp = tid >> 5, lane = tid & 31;
    int tok = blockIdx.x * 8 + warp;
    if (tok < s) {
        const float* xr = x + (size_t)tok * M_;
        float acc[E_];
#pragma unroll
        for (int e = 0; e < E_; e++) acc[e] = 0.0f;
        for (int k = lane; k < M_; k += 32) {
            float xv = xr[k];
#pragma unroll
            for (int e = 0; e < E_; e++) acc[e] += xv * swg[k * E_ + e];
        }
#pragma unroll
        for (int off = 16; off; off >>= 1)
#pragma unroll
            for (int e = 0; e < E_; e++)
                acc[e] += __shfl_down_sync(0xffffffffu, acc[e], off);
        if (lane == 0) {
            float mx = acc[0]; int am = 0;
#pragma unroll
            for (int e = 1; e < E_; e++) if (acc[e] > mx) { mx = acc[e]; am = e; }
            float g[E_]; float sum = 0.0f;
#pragma unroll
            for (int e = 0; e < E_; e++) { g[e] = expf(acc[e] - mx); sum += g[e]; }
            float inv = 1.0f / sum;
            g_idx[tok]  = am;
            g_gate[tok] = g[am] * inv;
#pragma unroll
            for (int e = 0; e < E_; e++) atomicAdd(&bsum[e], g[e] * inv);
        }
    }
    __syncthreads();
    if (tid < E_) atomicAdd(&g_gate_sums[tid], bsum[tid]);
}

// ---------------- routing scan (validated R1) -------------------------------------
__global__ __launch_bounds__(256) void scan_kernel(int s, int capacity,
                                                   float* __restrict__ out, long long out_size) {
    __shared__ int cnt[256][E_];
    __shared__ int totals[E_];
    int tid = threadIdx.x;
    int chunk = (s + 255) / 256;
    int lo = tid * chunk, hi = lo + chunk; if (hi > s) hi = s;
    int c[E_];
#pragma unroll
    for (int e = 0; e < E_; e++) c[e] = 0;
    for (int t = lo; t < hi; t++) c[g_idx[t]]++;
#pragma unroll
    for (int e = 0; e < E_; e++) cnt[tid][e] = c[e];
    __syncthreads();
    if (tid < E_) {
        int run = 0;
        for (int i = 0; i < 256; i++) { int v = cnt[i][tid]; cnt[i][tid] = run; run += v; }
        totals[tid] = run;
        g_kept[tid] = run < capacity ? run : capacity;
    }
    __syncthreads();
    int base[E_];
#pragma unroll
    for (int e = 0; e < E_; e++) base[e] = cnt[tid][e];
    for (int t = lo; t < hi; t++) {
        int e = g_idx[t];
        int loc = base[e]++;
        if (loc < capacity) {
            g_slot_token[e * CAP + loc] = t;
            g_slot_gate [e * CAP + loc] = g_gate[t];
        }
    }
    if (tid == 0 && out_size > (long long)s * M_) {
        float la = 0.0f, inv_s = 1.0f / (float)s;
        for (int e = 0; e < E_; e++)
            la += (g_gate_sums[e] * inv_s) * ((float)totals[e] * inv_s);
        la *= (float)E_;
        long long off = (long long)s * M_;
        out[off] = la;
        for (int e = 0; e < E_; e++) out[off + 1 + e] = (float)totals[e];
    }
}

// ---------------- shared GEMM inner: 64x128 tile, BK=16, FMA2 ----------------------
// As rows: 64 floats padded to 68; Bs rows: 128 floats padded to 132.
#define AR 68
#define BR 132

__device__ __forceinline__ void inner_tile(const float (*As)[AR],
                                           const float (*Bs)[BR],
                                           int tx, int ty, u64 acc2[4][4]) {
#pragma unroll
    for (int kk = 0; kk < 16; kk++) {
        float4 a0 = *(const float4*)&As[kk][ty * 4];
        float4 b0 = *(const float4*)&Bs[kk][tx * 4];
        float4 b1 = *(const float4*)&Bs[kk][64 + tx * 4];
        u64 aa[4], bb[4];
        DUP2(aa[0], a0.x); DUP2(aa[1], a0.y); DUP2(aa[2], a0.z); DUP2(aa[3], a0.w);
        bb[0] = ((const u64*)&b0)[0]; bb[1] = ((const u64*)&b0)[1];
        bb[2] = ((const u64*)&b1)[0]; bb[3] = ((const u64*)&b1)[1];
#pragma unroll
        for (int i = 0; i < 4; i++)
#pragma unroll
            for (int j = 0; j < 4; j++)
                FMA2(acc2[i][j], aa[i], bb[j]);
    }
}

// transpose-store prefetched A regs (1 float4 per thread covers 64 rows x 16 k)
__device__ __forceinline__ void stage_storeA(float (*As)[AR], float4 pa, int tid) {
    int row = tid >> 2, kk = (tid & 3) * 4;
    As[kk + 0][row] = pa.x; As[kk + 1][row] = pa.y;
    As[kk + 2][row] = pa.z; As[kk + 3][row] = pa.w;
}

// ---------------- GEMM1: h = gelu(gather(x) @ w1[e] + b1[e]) -----------------------
__global__ __launch_bounds__(256, 2) void gemm1_kernel(const float* __restrict__ x,
                                                       const float* __restrict__ w1,
                                                       const float* __restrict__ b1,
                                                       int capacity) {
    const int e = blockIdx.z;
    const int kept = g_kept[e];
    const int m0 = blockIdx.y * 64;
    if (m0 >= kept) return;
    const int n0 = blockIdx.x * 128;

    __shared__ float As[2][16][AR];
    __shared__ float Bs[2][16][BR];
    __shared__ int   tok[64];

    int tid = threadIdx.x;
    if (tid < 64) {
        int r = m0 + tid;
        tok[tid] = (r < kept) ? g_slot_token[e * capacity + r] : -1;
    }
    __syncthreads();

    const float* w1e = w1 + (size_t)e * M_ * H_;
    u64 acc2[4][4];
#pragma unroll
    for (int i = 0; i < 4; i++)
#pragma unroll
        for (int j = 0; j < 4; j++) acc2[i][j] = 0ull;

    int tx = tid & 15, ty = tid >> 4;

    // per-thread coords: A (1 slot, transposed store), B (2 slots, cp.async)
    int arow = tid >> 2, akk = (tid & 3) * 4;
    int t_a = tok[arow];
    const float* aptr = (t_a >= 0) ? (x + (size_t)t_a * M_ + akk) : 0;
    int bbk0 = tid >> 5,          bbn0 = (tid & 31) * 4;
    int bbk1 = (tid + 256) >> 5,  bbn1 = ((tid + 256) & 31) * 4;
    const float* bptr0 = w1e + (size_t)bbk0 * H_ + n0 + bbn0;
    const float* bptr1 = w1e + (size_t)bbk1 * H_ + n0 + bbn1;
    uint32_t bs0[2], bs1[2];
#pragma unroll
    for (int b = 0; b < 2; b++) {
        bs0[b] = smem_u32(&Bs[b][bbk0][bbn0]);
        bs1[b] = smem_u32(&Bs[b][bbk1][bbn1]);
    }

    // prologue: stage 0
    float4 pa = aptr ? *(const float4*)aptr : make_float4(0.f, 0.f, 0.f, 0.f);
    cp16(bs0[0], bptr0);
    cp16(bs1[0], bptr1);
    CP_COMMIT();
    stage_storeA(As[0], pa, tid);
    CP_WAIT0();
    __syncthreads();

    const int nk = M_ / 16;   // 64 stages
    for (int s = 0; s < nk; s++) {
        int buf = s & 1;
        if (s + 1 < nk) {
            int k0 = (s + 1) * 16;
            pa = aptr ? *(const float4*)(aptr + k0) : make_float4(0.f, 0.f, 0.f, 0.f);
            cp16(bs0[buf ^ 1], bptr0 + (size_t)k0 * H_);
            cp16(bs1[buf ^ 1], bptr1 + (size_t)k0 * H_);
            CP_COMMIT();
        }
        inner_tile(As[buf], Bs[buf], tx, ty, acc2);
        if (s + 1 < nk) stage_storeA(As[buf ^ 1], pa, tid);
        CP_WAIT0();
        __syncthreads();
    }

    const float* b1e = b1 + e * H_;
#pragma unroll
    for (int i = 0; i < 4; i++) {
        int r = m0 + ty * 4 + i;
        if (r < kept) {
            float* hrow = g_h + ((size_t)e * CAP + r) * H_;
#pragma unroll
            for (int j = 0; j < 4; j++) {
                int n = n0 + (j < 2 ? tx * 4 + j * 2 : 64 + tx * 4 + (j - 2) * 2);
                float p0 = __uint_as_float((uint32_t)acc2[i][j]);
                float p1 = __uint_as_float((uint32_t)(acc2[i][j] >> 32));
                float v0 = p0 + b1e[n];
                float v1 = p1 + b1e[n + 1];
                float u0 = 0.7978845608028654f * (v0 + 0.044715f * v0 * v0 * v0);
                float u1 = 0.7978845608028654f * (v1 + 0.044715f * v1 * v1 * v1);
                hrow[n]     = 0.5f * v0 * (1.0f + tanhf(u0));
                hrow[n + 1] = 0.5f * v1 * (1.0f + tanhf(u1));
            }
        }
    }
}

// ---------------- GEMM2: out[token] = (h @ w2[e] + b2[e]) * gate --------------------
__global__ __launch_bounds__(256, 2) void gemm2_kernel(const float* __restrict__ w2,
                                                       const float* __restrict__ b2,
                                                       float* __restrict__ out,
                                                       int capacity) {
    const int e = blockIdx.z;
    const int kept = g_kept[e];
    const int m0 = blockIdx.y * 64;
    if (m0 >= kept) return;
    const int n0 = blockIdx.x * 128;

    __shared__ float As[2][16][AR];
    __shared__ float Bs[2][16][BR];

    int tid = threadIdx.x;
    const float* w2e  = w2 + (size_t)e * H_ * M_;
    const float* hblk = g_h + ((size_t)e * CAP + m0) * H_;

    u64 acc2[4][4];
#pragma unroll
    for (int i = 0; i < 4; i++)
#pragma unroll
        for (int j = 0; j < 4; j++) acc2[i][j] = 0ull;

    int tx = tid & 15, ty = tid >> 4;

    int arow = tid >> 2, akk = (tid & 3) * 4;
    // rows >= kept read stale scratch; results for them are never stored
    const float* aptr = hblk + (size_t)arow * H_ + akk;
    int bbk0 = tid >> 5,          bbn0 = (tid & 31) * 4;
    int bbk1 = (tid + 256) >> 5,  bbn1 = ((tid + 256) & 31) * 4;
    const float* bptr0 = w2e + (size_t)bbk0 * M_ + n0 + bbn0;
    const float* bptr1 = w2e + (size_t)bbk1 * M_ + n0 + bbn1;
    uint32_t bs0[2], bs1[2];
#pragma unroll
    for (int b = 0; b < 2; b++) {
        bs0[b] = smem_u32(&Bs[b][bbk0][bbn0]);
        bs1[b] = smem_u32(&Bs[b][bbk1][bbn1]);
    }

    float4 pa = *(const float4*)aptr;
    cp16(bs0[0], bptr0);
    cp16(bs1[0], bptr1);
    CP_COMMIT();
    stage_storeA(As[0], pa, tid);
    CP_WAIT0();
    __syncthreads();

    const int nk = H_ / 16;   // 256 stages
    for (int s = 0; s < nk; s++) {
        int buf = s & 1;
        if (s + 1 < nk) {
            int k0 = (s + 1) * 16;
            pa = *(const float4*)(aptr + k0);
            cp16(bs0[buf ^ 1], bptr0 + (size_t)k0 * M_);
            cp16(bs1[buf ^ 1], bptr1 + (size_t)k0 * M_);
            CP_COMMIT();
        }
        inner_tile(As[buf], Bs[buf], tx, ty, acc2);
        if (s + 1 < nk) stage_storeA(As[buf ^ 1], pa, tid);
        CP_WAIT0();
        __syncthreads();
    }

    const float* b2e = b2 + e * M_;
#pragma unroll
    for (int i = 0; i < 4; i++) {
        int r = m0 + ty * 4 + i;
        if (r < kept) {
            int t = g_slot_token[e * capacity + r];
            float gate = g_slot_gate[e * capacity + r];
            float* orow = out + (size_t)t * M_;
#pragma unroll
            for (int j = 0; j < 4; j++) {
                int n = n0 + (j < 2 ? tx * 4 + j * 2 : 64 + tx * 4 + (j - 2) * 2);
                float p0 = __uint_as_float((uint32_t)acc2[i][j]);
                float p1 = __uint_as_float((uint32_t)(acc2[i][j] >> 32));
                orow[n]     = (p0 + b2e[n])     * gate;
                orow[n + 1] = (p1 + b2e[n + 1]) * gate;
            }
        }
    }
}

// ---------------- launch -------------------------------------------------------
extern "C" void kernel_launch(void* const* d_in, const int* in_sizes, int n_in,
                              void* d_out, int out_size) {
    const float* x  = (const float*)d_in[0];
    const float* wg = (const float*)d_in[1];
    const float* w1 = (const float*)d_in[2];
    const float* b1 = (const float*)d_in[3];
    const float* w2 = (const float*)d_in[4];
    const float* b2 = (const float*)d_in[5];
    float* out = (float*)d_out;

    int s = in_sizes[0] / M_;
    int capacity = (s + E_ - 1) / E_;
    if (capacity < 4) capacity = 4;
    if (capacity > CAP) capacity = CAP;

    cudaMemsetAsync(d_out, 0, (size_t)out_size * sizeof(float), 0);

    init_kernel<<<1, 32>>>();
    gate_kernel<<<(s + 7) / 8, 256>>>(x, wg, s);
    scan_kernel<<<1, 256>>>(s, capacity, out, (long long)out_size);

    dim3 g1(H_ / 128, (capacity + 63) / 64, E_);
    gemm1_kernel<<<g1, 256>>>(x, w1, b1, capacity);

    dim3 g2(M_ / 128, (capacity + 63) / 64, E_);
    gemm2_kernel<<<g2, 256>>>(w2, b2, out, capacity);
}

// round 17
// speedup vs baseline: 1.2314x; 1.2314x over previous
#include <cuda_runtime.h>
#include <cuda_bf16.h>
#include <stdint.h>
#include <math.h>

#define E_   8
#define M_   1024
#define H_   4096
#define SMAX 16384
#define CAP  2048

// ---------------- device scratch ------------------------------------------------
__device__ int   g_idx[SMAX];
__device__ float g_gate[SMAX];
__device__ float g_gate_sums[E_];
__device__ int   g_kept[E_];
__device__ int   g_slot_token[E_ * CAP];
__device__ float g_slot_gate[E_ * CAP];
__device__ float g_h[(size_t)E_ * CAP * H_];   // fp32 intermediate activations

typedef unsigned long long u64;

#define FMA2(c, a, b) \
    asm("fma.rn.f32x2 %0, %1, %2, %0;" : "+l"(c) : "l"(a), "l"(b))
#define DUP2(d, v) \
    asm("mov.b64 %0, {%1, %1};" : "=l"(d) : "f"(v))

__device__ __forceinline__ uint32_t smem_u32(const void* p) {
    uint32_t a;
    asm("{ .reg .u64 t; cvta.to.shared.u64 t, %1; cvt.u32.u64 %0, t; }" : "=r"(a) : "l"(p));
    return a;
}
__device__ __forceinline__ void cp16(uint32_t dst, const void* src) {
    asm volatile("cp.async.cg.shared.global [%0], [%1], 16;" :: "r"(dst), "l"(src));
}
#define CP_COMMIT() asm volatile("cp.async.commit_group;" ::: "memory")
#define CP_WAIT0()  asm volatile("cp.async.wait_group 0;" ::: "memory")
#define CP_WAIT1()  asm volatile("cp.async.wait_group 1;" ::: "memory")

// ---------------- init ----------------------------------------------------------
__global__ void init_kernel() {
    if (threadIdx.x < E_) g_gate_sums[threadIdx.x] = 0.0f;
}

// ---------------- gating (validated R1) ------------------------------------------
__global__ __launch_bounds__(256) void gate_kernel(const float* __restrict__ x,
                                                   const float* __restrict__ wg, int s) {
    __shared__ float swg[M_ * E_];
    __shared__ float bsum[E_];
    int tid = threadIdx.x;
    for (int i = tid; i < M_ * E_; i += 256) swg[i] = wg[i];
    if (tid < E_) bsum[tid] = 0.0f;
    __syncthreads();
    int warp = tid >> 5, lane = tid & 31;
    int tok = blockIdx.x * 8 + warp;
    if (tok < s) {
        const float* xr = x + (size_t)tok * M_;
        float acc[E_];
#pragma unroll
        for (int e = 0; e < E_; e++) acc[e] = 0.0f;
        for (int k = lane; k < M_; k += 32) {
            float xv = xr[k];
#pragma unroll
            for (int e = 0; e < E_; e++) acc[e] += xv * swg[k * E_ + e];
        }
#pragma unroll
        for (int off = 16; off; off >>= 1)
#pragma unroll
            for (int e = 0; e < E_; e++)
                acc[e] += __shfl_down_sync(0xffffffffu, acc[e], off);
        if (lane == 0) {
            float mx = acc[0]; int am = 0;
#pragma unroll
            for (int e = 1; e < E_; e++) if (acc[e] > mx) { mx = acc[e]; am = e; }
            float g[E_]; float sum = 0.0f;
#pragma unroll
            for (int e = 0; e < E_; e++) { g[e] = expf(acc[e] - mx); sum += g[e]; }
            float inv = 1.0f / sum;
            g_idx[tok]  = am;
            g_gate[tok] = g[am] * inv;
#pragma unroll
            for (int e = 0; e < E_; e++) atomicAdd(&bsum[e], g[e] * inv);
        }
    }
    __syncthreads();
    if (tid < E_) atomicAdd(&g_gate_sums[tid], bsum[tid]);
}

// ---------------- routing scan (validated R1) -------------------------------------
__global__ __launch_bounds__(256) void scan_kernel(int s, int capacity,
                                                   float* __restrict__ out, long long out_size) {
    __shared__ int cnt[256][E_];
    __shared__ int totals[E_];
    int tid = threadIdx.x;
    int chunk = (s + 255) / 256;
    int lo = tid * chunk, hi = lo + chunk; if (hi > s) hi = s;
    int c[E_];
#pragma unroll
    for (int e = 0; e < E_; e++) c[e] = 0;
    for (int t = lo; t < hi; t++) c[g_idx[t]]++;
#pragma unroll
    for (int e = 0; e < E_; e++) cnt[tid][e] = c[e];
    __syncthreads();
    if (tid < E_) {
        int run = 0;
        for (int i = 0; i < 256; i++) { int v = cnt[i][tid]; cnt[i][tid] = run; run += v; }
        totals[tid] = run;
        g_kept[tid] = run < capacity ? run : capacity;
    }
    __syncthreads();
    int base[E_];
#pragma unroll
    for (int e = 0; e < E_; e++) base[e] = cnt[tid][e];
    for (int t = lo; t < hi; t++) {
        int e = g_idx[t];
        int loc = base[e]++;
        if (loc < capacity) {
            g_slot_token[e * CAP + loc] = t;
            g_slot_gate [e * CAP + loc] = g_gate[t];
        }
    }
    if (tid == 0 && out_size > (long long)s * M_) {
        float la = 0.0f, inv_s = 1.0f / (float)s;
        for (int e = 0; e < E_; e++)
            la += (g_gate_sums[e] * inv_s) * ((float)totals[e] * inv_s);
        la *= (float)E_;
        long long off = (long long)s * M_;
        out[off] = la;
        for (int e = 0; e < E_; e++) out[off + 1 + e] = (float)totals[e];
    }
}

// ---------------- shared GEMM inner: 128x128 tile, BK=16, FMA2 (R15-validated) ------
#define SROW 132

__device__ __forceinline__ void inner_tile16(const float (*As)[SROW],
                                             const float (*Bs)[SROW],
                                             int tx, int ty, u64 acc2[8][4]) {
#pragma unroll
    for (int kk = 0; kk < 16; kk++) {
        float4 a0 = *(const float4*)&As[kk][ty * 4];
        float4 a1 = *(const float4*)&As[kk][64 + ty * 4];
        float4 b0 = *(const float4*)&Bs[kk][tx * 4];
        float4 b1 = *(const float4*)&Bs[kk][64 + tx * 4];
        u64 aa[8], bb[4];
        DUP2(aa[0], a0.x); DUP2(aa[1], a0.y); DUP2(aa[2], a0.z); DUP2(aa[3], a0.w);
        DUP2(aa[4], a1.x); DUP2(aa[5], a1.y); DUP2(aa[6], a1.z); DUP2(aa[7], a1.w);
        bb[0] = ((const u64*)&b0)[0]; bb[1] = ((const u64*)&b0)[1];
        bb[2] = ((const u64*)&b1)[0]; bb[3] = ((const u64*)&b1)[1];
#pragma unroll
        for (int i = 0; i < 8; i++)
#pragma unroll
            for (int j = 0; j < 4; j++)
                FMA2(acc2[i][j], aa[i], bb[j]);
    }
}

// transpose-store prefetched A regs (2 float4 per thread covers 128 rows x 16 k)
__device__ __forceinline__ void stage_storeA(float (*As)[SROW],
                                             const float4 pa[2], int tid) {
#pragma unroll
    for (int i = 0; i < 2; i++) {
        int slot = tid + i * 256;
        int row = slot >> 2, kk = (slot & 3) * 4;
        As[kk + 0][row] = pa[i].x; As[kk + 1][row] = pa[i].y;
        As[kk + 2][row] = pa[i].z; As[kk + 3][row] = pa[i].w;
    }
}

// ---------------- GEMM1: h = gelu(gather(x) @ w1[e] + b1[e]) -----------------------
__global__ __launch_bounds__(256, 2) void gemm1_kernel(const float* __restrict__ x,
                                                       const float* __restrict__ w1,
                                                       const float* __restrict__ b1,
                                                       int capacity) {
    const int e = blockIdx.z;
    const int kept = g_kept[e];
    const int m0 = blockIdx.y * 128;
    if (m0 >= kept) return;
    const int n0 = blockIdx.x * 128;

    __shared__ float As[2][16][SROW];
    __shared__ float Bs[3][16][SROW];
    __shared__ int   tok[128];

    int tid = threadIdx.x;
    if (tid < 128) {
        int r = m0 + tid;
        tok[tid] = (r < kept) ? g_slot_token[e * capacity + r] : -1;
    }
    __syncthreads();

    const float* w1e = w1 + (size_t)e * M_ * H_;
    u64 acc2[8][4];
#pragma unroll
    for (int i = 0; i < 8; i++)
#pragma unroll
        for (int j = 0; j < 4; j++) acc2[i][j] = 0ull;

    int tx = tid & 15, ty = tid >> 4;

    int arow0 = tid >> 2,         akk0 = (tid & 3) * 4;
    int arow1 = (tid + 256) >> 2, akk1 = ((tid + 256) & 3) * 4;
    int t_a0 = tok[arow0], t_a1 = tok[arow1];
    const float* aptr0 = (t_a0 >= 0) ? (x + (size_t)t_a0 * M_ + akk0) : 0;
    const float* aptr1 = (t_a1 >= 0) ? (x + (size_t)t_a1 * M_ + akk1) : 0;
    int bbk0 = tid >> 5,          bbn0 = (tid & 31) * 4;
    int bbk1 = (tid + 256) >> 5,  bbn1 = ((tid + 256) & 31) * 4;
    const float* bptr0 = w1e + (size_t)bbk0 * H_ + n0 + bbn0;
    const float* bptr1 = w1e + (size_t)bbk1 * H_ + n0 + bbn1;
    uint32_t bs0[3], bs1[3];
#pragma unroll
    for (int b = 0; b < 3; b++) {
        bs0[b] = smem_u32(&Bs[b][bbk0][bbn0]);
        bs1[b] = smem_u32(&Bs[b][bbk1][bbn1]);
    }

    const int nk = M_ / 16;   // 64 stages
    // prologue: B(0), B(1) in flight; A(0) staged
    float4 pa[2];
    pa[0] = aptr0 ? *(const float4*)aptr0 : make_float4(0.f, 0.f, 0.f, 0.f);
    pa[1] = aptr1 ? *(const float4*)aptr1 : make_float4(0.f, 0.f, 0.f, 0.f);
    cp16(bs0[0], bptr0); cp16(bs1[0], bptr1); CP_COMMIT();
    cp16(bs0[1], bptr0 + (size_t)16 * H_); cp16(bs1[1], bptr1 + (size_t)16 * H_); CP_COMMIT();
    stage_storeA(As[0], pa, tid);
    CP_WAIT1();           // B(0) done
    __syncthreads();

    int bcur = 0, bnext2 = 2;
    for (int s = 0; s < nk; s++) {
        int abuf = s & 1;
        if (s + 2 < nk) {
            size_t k0 = (size_t)(s + 2) * 16;
            cp16(bs0[bnext2], bptr0 + k0 * H_);
            cp16(bs1[bnext2], bptr1 + k0 * H_);
            CP_COMMIT();
        }
        if (s + 1 < nk) {
            int k0 = (s + 1) * 16;
            pa[0] = aptr0 ? *(const float4*)(aptr0 + k0) : make_float4(0.f, 0.f, 0.f, 0.f);
            pa[1] = aptr1 ? *(const float4*)(aptr1 + k0) : make_float4(0.f, 0.f, 0.f, 0.f);
        }
        inner_tile16(As[abuf], Bs[bcur], tx, ty, acc2);
        if (s + 1 < nk) stage_storeA(As[abuf ^ 1], pa, tid);
        if (s + 2 < nk) { CP_WAIT1(); } else { CP_WAIT0(); }
        __syncthreads();
        bcur = (bcur == 2) ? 0 : bcur + 1;
        bnext2 = (bnext2 == 2) ? 0 : bnext2 + 1;
    }

    const float* b1e = b1 + e * H_;
#pragma unroll
    for (int i = 0; i < 8; i++) {
        int r = m0 + (i < 4 ? ty * 4 + i : 64 + ty * 4 + (i - 4));
        if (r < kept) {
            float* hrow = g_h + ((size_t)e * CAP + r) * H_;
#pragma unroll
            for (int j = 0; j < 4; j++) {
                int n = n0 + (j < 2 ? tx * 4 + j * 2 : 64 + tx * 4 + (j - 2) * 2);
                float p0 = __uint_as_float((uint32_t)acc2[i][j]);
                float p1 = __uint_as_float((uint32_t)(acc2[i][j] >> 32));
                float v0 = p0 + b1e[n];
                float v1 = p1 + b1e[n + 1];
                float u0 = 0.7978845608028654f * (v0 + 0.044715f * v0 * v0 * v0);
                float u1 = 0.7978845608028654f * (v1 + 0.044715f * v1 * v1 * v1);
                hrow[n]     = 0.5f * v0 * (1.0f + tanhf(u0));
                hrow[n + 1] = 0.5f * v1 * (1.0f + tanhf(u1));
            }
        }
    }
}

// ---------------- GEMM2: out[token] = (h @ w2[e] + b2[e]) * gate --------------------
__global__ __launch_bounds__(256, 2) void gemm2_kernel(const float* __restrict__ w2,
                                                       const float* __restrict__ b2,
                                                       float* __restrict__ out,
                                                       int capacity) {
    const int e = blockIdx.z;
    const int kept = g_kept[e];
    const int m0 = blockIdx.y * 128;
    if (m0 >= kept) return;
    const int n0 = blockIdx.x * 128;

    __shared__ float As[2][16][SROW];
    __shared__ float Bs[3][16][SROW];

    int tid = threadIdx.x;
    const float* w2e  = w2 + (size_t)e * H_ * M_;
    const float* hblk = g_h + ((size_t)e * CAP + m0) * H_;

    u64 acc2[8][4];
#pragma unroll
    for (int i = 0; i < 8; i++)
#pragma unroll
        for (int j = 0; j < 4; j++) acc2[i][j] = 0ull;

    int tx = tid & 15, ty = tid >> 4;

    int arow0 = tid >> 2,         akk0 = (tid & 3) * 4;
    int arow1 = (tid + 256) >> 2, akk1 = ((tid + 256) & 3) * 4;
    // rows >= kept read stale scratch; results for them are never stored
    const float* aptr0 = hblk + (size_t)arow0 * H_ + akk0;
    const float* aptr1 = hblk + (size_t)arow1 * H_ + akk1;
    int bbk0 = tid >> 5,          bbn0 = (tid & 31) * 4;
    int bbk1 = (tid + 256) >> 5,  bbn1 = ((tid + 256) & 31) * 4;
    const float* bptr0 = w2e + (size_t)bbk0 * M_ + n0 + bbn0;
    const float* bptr1 = w2e + (size_t)bbk1 * M_ + n0 + bbn1;
    uint32_t bs0[3], bs1[3];
#pragma unroll
    for (int b = 0; b < 3; b++) {
        bs0[b] = smem_u32(&Bs[b][bbk0][bbn0]);
        bs1[b] = smem_u32(&Bs[b][bbk1][bbn1]);
    }

    const int nk = H_ / 16;   // 256 stages
    float4 pa[2];
    pa[0] = *(const float4*)aptr0;
    pa[1] = *(const float4*)aptr1;
    cp16(bs0[0], bptr0); cp16(bs1[0], bptr1); CP_COMMIT();
    cp16(bs0[1], bptr0 + (size_t)16 * M_); cp16(bs1[1], bptr1 + (size_t)16 * M_); CP_COMMIT();
    stage_storeA(As[0], pa, tid);
    CP_WAIT1();
    __syncthreads();

    int bcur = 0, bnext2 = 2;
    for (int s = 0; s < nk; s++) {
        int abuf = s & 1;
        if (s + 2 < nk) {
            size_t k0 = (size_t)(s + 2) * 16;
            cp16(bs0[bnext2], bptr0 + k0 * M_);
            cp16(bs1[bnext2], bptr1 + k0 * M_);
            CP_COMMIT();
        }
        if (s + 1 < nk) {
            int k0 = (s + 1) * 16;
            pa[0] = *(const float4*)(aptr0 + k0);
            pa[1] = *(const float4*)(aptr1 + k0);
        }
        inner_tile16(As[abuf], Bs[bcur], tx, ty, acc2);
        if (s + 1 < nk) stage_storeA(As[abuf ^ 1], pa, tid);
        if (s + 2 < nk) { CP_WAIT1(); } else { CP_WAIT0(); }
        __syncthreads();
        bcur = (bcur == 2) ? 0 : bcur + 1;
        bnext2 = (bnext2 == 2) ? 0 : bnext2 + 1;
    }

    const float* b2e = b2 + e * M_;
#pragma unroll
    for (int i = 0; i < 8; i++) {
        int r = m0 + (i < 4 ? ty * 4 + i : 64 + ty * 4 + (i - 4));
        if (r < kept) {
            int t = g_slot_token[e * capacity + r];
            float gate = g_slot_gate[e * capacity + r];
            float* orow = out + (size_t)t * M_;
#pragma unroll
            for (int j = 0; j < 4; j++) {
                int n = n0 + (j < 2 ? tx * 4 + j * 2 : 64 + tx * 4 + (j - 2) * 2);
                float p0 = __uint_as_float((uint32_t)acc2[i][j]);
                float p1 = __uint_as_float((uint32_t)(acc2[i][j] >> 32));
                orow[n]     = (p0 + b2e[n])     * gate;
                orow[n + 1] = (p1 + b2e[n + 1]) * gate;
            }
        }
    }
}

// ---------------- launch -------------------------------------------------------
extern "C" void kernel_launch(void* const* d_in, const int* in_sizes, int n_in,
                              void* d_out, int out_size) {
    const float* x  = (const float*)d_in[0];
    const float* wg = (const float*)d_in[1];
    const float* w1 = (const float*)d_in[2];
    const float* b1 = (const float*)d_in[3];
    const float* w2 = (const float*)d_in[4];
    const float* b2 = (const float*)d_in[5];
    float* out = (float*)d_out;

    int s = in_sizes[0] / M_;
    int capacity = (s + E_ - 1) / E_;
    if (capacity < 4) capacity = 4;
    if (capacity > CAP) capacity = CAP;

    cudaMemsetAsync(d_out, 0, (size_t)out_size * sizeof(float), 0);

    init_kernel<<<1, 32>>>();
    gate_kernel<<<(s + 7) / 8, 256>>>(x, wg, s);
    scan_kernel<<<1, 256>>>(s, capacity, out, (long long)out_size);

    dim3 g1(H_ / 128, (capacity + 127) / 128, E_);
    gemm1_kernel<<<g1, 256>>>(x, w1, b1, capacity);

    dim3 g2(M_ / 128, (capacity + 127) / 128, E_);
    gemm2_kernel<<<g2, 256>>>(w2, b2, out, capacity);
}